// round 4
// baseline (speedup 1.0000x reference)
#include <cuda_runtime.h>
#include <math_constants.h>

#define BB 8
#define NN 4096
#define KNN 20
#define EPSV 1e-5f
#define SLOPE 0.2f
#define NTOT ((float)(BB*NN*KNN))
#define PTS 32

typedef unsigned long long ull;

__device__ __forceinline__ void fma2(ull& d, ull a, ull b) {
    asm("fma.rn.f32x2 %0, %1, %2, %0;" : "+l"(d) : "l"(a), "l"(b));
}
__device__ __forceinline__ ull add2(ull a, ull b) {
    ull r; asm("add.rn.f32x2 %0, %1, %2;" : "=l"(r) : "l"(a), "l"(b)); return r;
}
__device__ __forceinline__ ull pack2(float lo, float hi) {
    ull r; asm("mov.b64 %0, {%1, %2};" : "=l"(r) : "f"(lo), "f"(hi)); return r;
}
__device__ __forceinline__ void unpack2(ull v, float& lo, float& hi) {
    asm("mov.b64 {%0, %1}, %2;" : "=f"(lo), "=f"(hi) : "l"(v));
}

__device__ int   g_idx[BB*NN*KNN];
__device__ float g_mom[27];
__device__ float g_scale1[64], g_shift1[64];
__device__ float g_sum2[64], g_sumsq2[64];
__device__ float g_scale2[64], g_shift2[64];
__device__ float g_maxb[BB*NN*64];
__device__ float g_minb[BB*NN*64];

__global__ void zero_kernel() {
    int t = threadIdx.x;
    if (t < 27) g_mom[t] = 0.f;
    if (t < 64) { g_sum2[t] = 0.f; g_sumsq2[t] = 0.f; }
}

// Branchless PARALLEL insertion (depth ~2, not a 20-swap chain).
__device__ __forceinline__ void insert20(float (&dl)[KNN], int (&il)[KNN],
                                         float dd, int m) {
#pragma unroll
    for (int j = KNN - 1; j >= 1; j--) {
        bool b1 = dd < dl[j - 1];
        bool b2 = dd < dl[j];
        dl[j] = b1 ? dl[j - 1] : (b2 ? dd : dl[j]);
        il[j] = b1 ? il[j - 1] : (b2 ? m  : il[j]);
    }
    bool b0 = dd < dl[0];
    dl[0] = b0 ? dd : dl[0];
    il[0] = b0 ? m  : il[0];
}

// KNN: 64 queries/block, 4 m-partitions of 1024 pts per query (one thread each).
// Per-thread smem candidate buffer, individual drains (no warp votes).
// Partition lists merged in partition order with strict '<' -> identical
// selection/tie semantics to a serial ascending-m scan.
__global__ __launch_bounds__(256) void knn_kernel(const float* __restrict__ x) {
    __shared__ float sx[NN], sy[NN], sz[NN];
    __shared__ unsigned short sbi[KNN][256];
    int b = blockIdx.y;
    int t = threadIdx.x;
    const float* xb = x + b * 3 * NN;
    for (int i = t; i < NN; i += 256) {
        sx[i] = xb[i];
        sy[i] = xb[NN + i];
        sz[i] = xb[2 * NN + i];
    }
    __syncthreads();

    int ql = t & 63;
    int part = t >> 6;
    int q = blockIdx.x * 64 + ql;
    float qx = sx[q], qy = sy[q], qz = sz[q];
    float dl[KNN]; int il[KNN];
#pragma unroll
    for (int j = 0; j < KNN; j++) { dl[j] = CUDART_INF_F; il[j] = 0; }

    int cnt = 0;
    int mbeg = part << 10;
    for (int m0 = mbeg; m0 < mbeg + 1024; m0 += 8) {
        float d[8];
#pragma unroll
        for (int u = 0; u < 8; u++) {
            int m = m0 + u;
            float dx = qx - sx[m], dy = qy - sy[m], dz = qz - sz[m];
            d[u] = fmaf(dx, dx, fmaf(dy, dy, dz * dz));
        }
        float thr = dl[KNN - 1];
#pragma unroll
        for (int u = 0; u < 8; u++) {
            if (d[u] < thr) { sbi[cnt][t] = (unsigned short)(m0 + u); cnt++; }
        }
        if (cnt > 12) {
            for (int i = 0; i < cnt; i++) {
                int m = sbi[i][t];
                float dx = qx - sx[m], dy = qy - sy[m], dz = qz - sz[m];
                float dd = fmaf(dx, dx, fmaf(dy, dy, dz * dz));
                if (dd < dl[KNN - 1]) insert20(dl, il, dd, m);
            }
            cnt = 0;
        }
    }
    for (int i = 0; i < cnt; i++) {
        int m = sbi[i][t];
        float dx = qx - sx[m], dy = qy - sy[m], dz = qz - sz[m];
        float dd = fmaf(dx, dx, fmaf(dy, dy, dz * dz));
        if (dd < dl[KNN - 1]) insert20(dl, il, dd, m);
    }

    __syncthreads();
    if (part != 0) {
#pragma unroll
        for (int j = 0; j < KNN; j++) sbi[j][t] = (unsigned short)il[j];
    }
    __syncthreads();

    if (part == 0) {
        for (int p = 1; p < 4; p++) {
            int col = ql + (p << 6);
#pragma unroll 4
            for (int j = 0; j < KNN; j++) {
                int m = sbi[j][col];
                float dx = qx - sx[m], dy = qy - sy[m], dz = qz - sz[m];
                float dd = fmaf(dx, dx, fmaf(dy, dy, dz * dz));
                if (dd < dl[KNN - 1]) insert20(dl, il, dd, m);
            }
        }

        int base = (b * NN + q) * KNN;
#pragma unroll
        for (int j = 0; j < KNN; j++) g_idx[base + j] = il[j];

        // Edge moments: first moment (6) + upper-tri second moment (21).
        float acc[27];
#pragma unroll
        for (int i = 0; i < 27; i++) acc[i] = 0.f;
#pragma unroll
        for (int j = 0; j < KNN; j++) {
            int m = il[j];
            float e[6];
            e[0] = sx[m] - qx; e[1] = sy[m] - qy; e[2] = sz[m] - qz;
            e[3] = qx; e[4] = qy; e[5] = qz;
            int tt = 6;
#pragma unroll
            for (int a = 0; a < 6; a++) {
                acc[a] += e[a];
#pragma unroll
                for (int bb = a; bb < 6; bb++) acc[tt++] += e[a] * e[bb];
            }
        }
#pragma unroll
        for (int i = 0; i < 27; i++) {
#pragma unroll
            for (int o = 16; o > 0; o >>= 1)
                acc[i] += __shfl_xor_sync(0xffffffffu, acc[i], o);
        }
        if ((t & 31) == 0) {
#pragma unroll
            for (int i = 0; i < 27; i++) atomicAdd(&g_mom[i], acc[i]);
        }
    }
}

__global__ void stats1_kernel(const float* __restrict__ W1,
                              const float* __restrict__ gamma1,
                              const float* __restrict__ beta1) {
    int c = threadIdx.x;
    if (c >= 64) return;
    float w[6];
#pragma unroll
    for (int j = 0; j < 6; j++) w[j] = W1[c * 6 + j];
    float m = 0.f;
#pragma unroll
    for (int j = 0; j < 6; j++) m += w[j] * g_mom[j];
    m /= NTOT;
    float qv = 0.f;
    int t = 6;
#pragma unroll
    for (int a = 0; a < 6; a++) {
#pragma unroll
        for (int bb = a; bb < 6; bb++) {
            float coef = (a == bb) ? 1.f : 2.f;
            qv += coef * w[a] * w[bb] * g_mom[t++];
        }
    }
    qv /= NTOT;
    float var = qv - m * m;
    float s = gamma1[c] * rsqrtf(var + EPSV);
    g_scale1[c] = s;
    g_shift1[c] = fmaf(-m, s, beta1[c]);
}

// Main fused kernel, j-half split GEMV:
// 256 threads = 2 point-halves x (4 warps x [16 channels x 2 j-halves]).
// Lane pair (xor 1) holds the two dot-halves of one channel; one shfl combines.
// sg row: half0 at [0..31], half1 at [36..67] (+144B => distinct banks, the
// paired broadcast loads coalesce into one wavefront).
__global__ __launch_bounds__(256, 3) void main_kernel(const float* __restrict__ x,
                                                      const float* __restrict__ W1,
                                                      const float* __restrict__ W2) {
    __shared__ __align__(16) float sedge[2][KNN][8];
    __shared__ __align__(16) float sg[2][KNN][68];
    __shared__ float schanS[64], schanQ[64];

    int tid = threadIdx.x;
    int h = tid >> 7;          // point-half
    int t = tid & 127;
    int lane = t & 31;
    int jh = lane & 1;         // j-half
    int cg = ((t >> 5) << 4) + (lane >> 1);   // GEMV channel
    int ch = t & 63;           // h1-phase channel
    int kb = t >> 6;           // h1-phase k base

    int pt0 = blockIdx.x * PTS;
    int b = pt0 >> 12;
    int n0 = pt0 & (NN - 1);

    ull w2pk[16];
#pragma unroll
    for (int j = 0; j < 16; j++)
        w2pk[j] = pack2(W2[cg * 64 + jh * 32 + 2 * j],
                        W2[cg * 64 + jh * 32 + 2 * j + 1]);
    float w1row[6];
#pragma unroll
    for (int j = 0; j < 6; j++) w1row[j] = W1[ch * 6 + j];
    float s1 = g_scale1[ch], sh1 = g_shift1[ch];
    float sum2 = 0.f, ssq2 = 0.f;
    const float* xb = x + b * 3 * NN;
    int col = (ch < 32) ? ch : (ch + 4);

    if (tid < 64) { schanS[tid] = 0.f; schanQ[tid] = 0.f; }

    for (int p = 0; p < PTS; p += 2) {
        int pt = n0 + p + h;
        int gi = b * NN + pt;
        __syncthreads();
        if (t < KNN) {
            int k = t;
            int nb = g_idx[gi * KNN + k];
            float qx = xb[pt], qy = xb[NN + pt], qz = xb[2 * NN + pt];
            float px = xb[nb], py = xb[NN + nb], pz = xb[2 * NN + nb];
            sedge[h][k][0] = px - qx;
            sedge[h][k][1] = py - qy;
            sedge[h][k][2] = pz - qz;
            sedge[h][k][3] = qx;
            sedge[h][k][4] = qy;
            sedge[h][k][5] = qz;
        }
        __syncthreads();
#pragma unroll
        for (int i = 0; i < 10; i++) {
            int k = kb + 2 * i;
            float hv = 0.f;
#pragma unroll
            for (int j = 0; j < 6; j++) hv = fmaf(sedge[h][k][j], w1row[j], hv);
            float v = fmaf(s1, hv, sh1);
            sg[h][k][col] = fmaxf(v, SLOPE * v);
        }
        __syncthreads();
        float mx = -CUDART_INF_F, mn = CUDART_INF_F;
#pragma unroll 2
        for (int k = 0; k < KNN; k++) {
            const ulonglong2* gp =
                reinterpret_cast<const ulonglong2*>(&sg[h][k][jh * 36]);
            ull a0 = 0ull, a1 = 0ull, a2 = 0ull, a3 = 0ull;
#pragma unroll
            for (int i = 0; i < 8; i += 2) {
                ulonglong2 gA = gp[i];
                ulonglong2 gB = gp[i + 1];
                fma2(a0, gA.x, w2pk[2 * i + 0]);
                fma2(a1, gA.y, w2pk[2 * i + 1]);
                fma2(a2, gB.x, w2pk[2 * i + 2]);
                fma2(a3, gB.y, w2pk[2 * i + 3]);
            }
            ull s = add2(add2(a0, a1), add2(a2, a3));
            float flo, fhi;
            unpack2(s, flo, fhi);
            float hsum = flo + fhi;
            float other = __shfl_xor_sync(0xffffffffu, hsum, 1);
            float hv = hsum + other;
            mx = fmaxf(mx, hv);
            mn = fminf(mn, hv);
            if (jh == 0) { sum2 += hv; ssq2 = fmaf(hv, hv, ssq2); }
        }
        if (jh == 0) {
            g_maxb[gi * 64 + cg] = mx;
            g_minb[gi * 64 + cg] = mn;
        }
    }

    __syncthreads();
    if (jh == 0) {
        atomicAdd(&schanS[cg], sum2);
        atomicAdd(&schanQ[cg], ssq2);
    }
    __syncthreads();
    if (tid < 64) {
        atomicAdd(&g_sum2[tid],   schanS[tid]);
        atomicAdd(&g_sumsq2[tid], schanQ[tid]);
    }
}

__global__ void stats2_kernel(const float* __restrict__ gamma2,
                              const float* __restrict__ beta2) {
    int c = threadIdx.x;
    if (c >= 64) return;
    float mean = g_sum2[c] / NTOT;
    float var = g_sumsq2[c] / NTOT - mean * mean;
    float s = gamma2[c] * rsqrtf(var + EPSV);
    g_scale2[c] = s;
    g_shift2[c] = fmaf(-mean, s, beta2[c]);
}

__global__ __launch_bounds__(256) void out_kernel(float* __restrict__ out) {
    __shared__ float tile[64][65];
    int b = blockIdx.y;
    int n0 = blockIdx.x * 64;
    int tid = threadIdx.x;
#pragma unroll
    for (int i = 0; i < 16; i++) {
        int flat = i * 256 + tid;
        int cc = flat & 63;
        int nl = flat >> 6;
        float s = g_scale2[cc];
        int gi = (b * NN + n0 + nl) * 64 + cc;
        float v;
        if (s >= 0.f) v = g_maxb[gi]; else v = g_minb[gi];
        float u = fmaf(s, v, g_shift2[cc]);
        tile[nl][cc] = fmaxf(u, SLOPE * u);
    }
    __syncthreads();
#pragma unroll
    for (int i = 0; i < 16; i++) {
        int flat = i * 256 + tid;
        int nl = flat & 63;
        int cc = flat >> 6;
        out[(b * 64 + cc) * NN + n0 + nl] = tile[nl][cc];
    }
}

extern "C" void kernel_launch(void* const* d_in, const int* in_sizes, int n_in,
                              void* d_out, int out_size) {
    const float* x      = (const float*)d_in[0];
    const float* W1     = (const float*)d_in[1];
    const float* gamma1 = (const float*)d_in[2];
    const float* beta1  = (const float*)d_in[3];
    const float* W2     = (const float*)d_in[4];
    const float* gamma2 = (const float*)d_in[5];
    const float* beta2  = (const float*)d_in[6];
    float* out = (float*)d_out;

    zero_kernel<<<1, 64>>>();
    knn_kernel<<<dim3(NN / 64, BB), 256>>>(x);
    stats1_kernel<<<1, 64>>>(W1, gamma1, beta1);
    main_kernel<<<BB * NN / PTS, 256>>>(x, W1, W2);
    stats2_kernel<<<1, 64>>>(gamma2, beta2);
    out_kernel<<<dim3(NN / 64, BB), 256>>>(out);
}

// round 5
// speedup vs baseline: 2.7903x; 2.7903x over previous
#include <cuda_runtime.h>
#include <math_constants.h>

#define BB 8
#define NN 4096
#define KNN 20
#define EPSV 1e-5f
#define SLOPE 0.2f
#define NTOT ((float)(BB*NN*KNN))
#define PTS 32

typedef unsigned long long ull;

__device__ __forceinline__ void fma2(ull& d, ull a, ull b) {
    asm("fma.rn.f32x2 %0, %1, %2, %0;" : "+l"(d) : "l"(a), "l"(b));
}
__device__ __forceinline__ ull add2(ull a, ull b) {
    ull r; asm("add.rn.f32x2 %0, %1, %2;" : "=l"(r) : "l"(a), "l"(b)); return r;
}
__device__ __forceinline__ ull pack2(float lo, float hi) {
    ull r; asm("mov.b64 %0, {%1, %2};" : "=l"(r) : "f"(lo), "f"(hi)); return r;
}
__device__ __forceinline__ void unpack2(ull v, float& lo, float& hi) {
    asm("mov.b64 {%0, %1}, %2;" : "=f"(lo), "=f"(hi) : "l"(v));
}
__device__ __forceinline__ void cp4(unsigned dst, const float* src) {
    asm volatile("cp.async.ca.shared.global [%0], [%1], 4;" :: "r"(dst), "l"(src));
}

__device__ int   g_idx[BB*NN*KNN];
__device__ float g_mom[27];
__device__ float g_scale1[64], g_shift1[64];
__device__ float g_sum2[64], g_sumsq2[64];
__device__ float g_scale2[64], g_shift2[64];
__device__ float g_maxb[BB*NN*64];
__device__ float g_minb[BB*NN*64];

__global__ void zero_kernel() {
    int t = threadIdx.x;
    if (t < 27) g_mom[t] = 0.f;
    if (t < 64) { g_sum2[t] = 0.f; g_sumsq2[t] = 0.f; }
}

// Branchless PARALLEL insertion (depth ~2, not a 20-swap chain).
__device__ __forceinline__ void insert20(float (&dl)[KNN], int (&il)[KNN],
                                         float dd, int m) {
#pragma unroll
    for (int j = KNN - 1; j >= 1; j--) {
        bool b1 = dd < dl[j - 1];
        bool b2 = dd < dl[j];
        dl[j] = b1 ? dl[j - 1] : (b2 ? dd : dl[j]);
        il[j] = b1 ? il[j - 1] : (b2 ? m  : il[j]);
    }
    bool b0 = dd < dl[0];
    dl[0] = b0 ? dd : dl[0];
    il[0] = b0 ? m  : il[0];
}

// KNN: 64 queries/block, 2 m-partitions of 2048 pts (thread per (query,part)).
// Candidates buffered in smem; drains are WARP-COLLECTIVE (vote) so the rare
// insertion path executes once per warp, not per lane. Partition lists merged
// in partition order (part0 m-range < part1 m-range) with strict '<' =>
// identical selection/tie semantics to a serial ascending-m scan.
__global__ __launch_bounds__(128) void knn_kernel(const float* __restrict__ x) {
    __shared__ float sx[NN], sy[NN], sz[NN];
    __shared__ unsigned short sbuf[KNN][128];
    __shared__ float mdist[KNN][64];
    __shared__ unsigned short midx[KNN][64];
    int b = blockIdx.y;
    int t = threadIdx.x;
    const float* xb = x + b * 3 * NN;
    for (int i = t; i < NN; i += 128) {
        sx[i] = xb[i];
        sy[i] = xb[NN + i];
        sz[i] = xb[2 * NN + i];
    }
    __syncthreads();

    int ql = t & 63;
    int part = t >> 6;
    int q = blockIdx.x * 64 + ql;
    float qx = sx[q], qy = sy[q], qz = sz[q];
    float dl[KNN]; int il[KNN];
#pragma unroll
    for (int j = 0; j < KNN; j++) { dl[j] = CUDART_INF_F; il[j] = 0; }

    int cnt = 0;
    int mbeg = part << 11;
    int mend = mbeg + 2048;
    for (int m0 = mbeg; m0 < mend; m0 += 8) {
        float d[8];
#pragma unroll
        for (int u = 0; u < 8; u++) {
            int m = m0 + u;
            float dx = qx - sx[m], dy = qy - sy[m], dz = qz - sz[m];
            d[u] = fmaf(dx, dx, fmaf(dy, dy, dz * dz));
        }
        float thr = dl[KNN - 1];
#pragma unroll
        for (int u = 0; u < 8; u++) {
            if (d[u] < thr) { sbuf[cnt][t] = (unsigned short)(m0 + u); cnt++; }
        }
        if (__any_sync(0xffffffffu, cnt > 12)) {
            for (int i = 0; i < cnt; i++) {
                int m = sbuf[i][t];
                float dx = qx - sx[m], dy = qy - sy[m], dz = qz - sz[m];
                float dd = fmaf(dx, dx, fmaf(dy, dy, dz * dz));
                if (dd < dl[KNN - 1]) insert20(dl, il, dd, m);
            }
            cnt = 0;
        }
    }
    for (int i = 0; i < cnt; i++) {
        int m = sbuf[i][t];
        float dx = qx - sx[m], dy = qy - sy[m], dz = qz - sz[m];
        float dd = fmaf(dx, dx, fmaf(dy, dy, dz * dz));
        if (dd < dl[KNN - 1]) insert20(dl, il, dd, m);
    }

    __syncthreads();
    if (part == 1) {
#pragma unroll
        for (int j = 0; j < KNN; j++) {
            mdist[j][ql] = dl[j];
            midx[j][ql] = (unsigned short)il[j];
        }
    }
    __syncthreads();

    if (part == 0) {
#pragma unroll 4
        for (int j = 0; j < KNN; j++) {
            float dd = mdist[j][ql];
            int m = midx[j][ql];
            if (dd < dl[KNN - 1]) insert20(dl, il, dd, m);
        }

        int base = (b * NN + q) * KNN;
#pragma unroll
        for (int j = 0; j < KNN; j++) g_idx[base + j] = il[j];

        // Edge moments: first moment (6) + upper-tri second moment (21).
        float acc[27];
#pragma unroll
        for (int i = 0; i < 27; i++) acc[i] = 0.f;
#pragma unroll
        for (int j = 0; j < KNN; j++) {
            int m = il[j];
            float e[6];
            e[0] = sx[m] - qx; e[1] = sy[m] - qy; e[2] = sz[m] - qz;
            e[3] = qx; e[4] = qy; e[5] = qz;
            int tt = 6;
#pragma unroll
            for (int a = 0; a < 6; a++) {
                acc[a] += e[a];
#pragma unroll
                for (int bb = a; bb < 6; bb++) acc[tt++] += e[a] * e[bb];
            }
        }
#pragma unroll
        for (int i = 0; i < 27; i++) {
#pragma unroll
            for (int o = 16; o > 0; o >>= 1)
                acc[i] += __shfl_xor_sync(0xffffffffu, acc[i], o);
        }
        if ((t & 31) == 0) {
#pragma unroll
            for (int i = 0; i < 27; i++) atomicAdd(&g_mom[i], acc[i]);
        }
    }
}

__global__ void stats1_kernel(const float* __restrict__ W1,
                              const float* __restrict__ gamma1,
                              const float* __restrict__ beta1) {
    int c = threadIdx.x;
    if (c >= 64) return;
    float w[6];
#pragma unroll
    for (int j = 0; j < 6; j++) w[j] = W1[c * 6 + j];
    float m = 0.f;
#pragma unroll
    for (int j = 0; j < 6; j++) m += w[j] * g_mom[j];
    m /= NTOT;
    float qv = 0.f;
    int t = 6;
#pragma unroll
    for (int a = 0; a < 6; a++) {
#pragma unroll
        for (int bb = a; bb < 6; bb++) {
            float coef = (a == bb) ? 1.f : 2.f;
            qv += coef * w[a] * w[bb] * g_mom[t++];
        }
    }
    qv /= NTOT;
    float var = qv - m * m;
    float s = gamma1[c] * rsqrtf(var + EPSV);
    g_scale1[c] = s;
    g_shift1[c] = fmaf(-m, s, beta1[c]);
}

// Main fused kernel with cp.async-pipelined neighbor gather.
// Raw coords {px,py,pz,qx,qy,qz} stream into sraw[next] during GEMV of the
// current pair; h1 uses transformed weights so no edge subtraction needed:
// (p-q).w012 + q.w345 == p.w012 + q.(w345-w012).
__global__ __launch_bounds__(256, 3) void main_kernel(const float* __restrict__ x,
                                                      const float* __restrict__ W1,
                                                      const float* __restrict__ W2) {
    __shared__ __align__(16) float sraw[2][2][KNN][8];
    __shared__ __align__(16) float sg[2][KNN][68];
    __shared__ float schanS[64], schanQ[64];

    int tid = threadIdx.x;
    int h = tid >> 7;          // point-half
    int t = tid & 127;
    int lane = t & 31;
    int jh = lane & 1;         // j-half
    int cg = ((t >> 5) << 4) + (lane >> 1);   // GEMV channel
    int ch = t & 63;           // h1-phase channel
    int kb = t >> 6;           // h1-phase k parity

    int pt0 = blockIdx.x * PTS;
    int b = pt0 >> 12;
    int n0 = pt0 & (NN - 1);

    ull w2pk[16];
#pragma unroll
    for (int j = 0; j < 16; j++)
        w2pk[j] = pack2(W2[cg * 64 + jh * 32 + 2 * j],
                        W2[cg * 64 + jh * 32 + 2 * j + 1]);
    float wt[6];
#pragma unroll
    for (int j = 0; j < 6; j++) wt[j] = W1[ch * 6 + j];
    wt[3] -= wt[0]; wt[4] -= wt[1]; wt[5] -= wt[2];
    float s1 = g_scale1[ch], sh1 = g_shift1[ch];
    float sum2 = 0.f, ssq2 = 0.f;
    const float* xb = x + b * 3 * NN;
    int col = (ch < 32) ? ch : (ch + 4);
    int gbase = b * NN;

    if (tid < 64) { schanS[tid] = 0.f; schanQ[tid] = 0.f; }

    bool gat = (t < KNN);
    int nbn = 0;
    if (gat) {
        int pt = n0 + h;
        int nb = g_idx[(gbase + pt) * KNN + t];
        unsigned sa = (unsigned)__cvta_generic_to_shared(&sraw[0][h][t][0]);
        cp4(sa + 0,  xb + nb);
        cp4(sa + 4,  xb + NN + nb);
        cp4(sa + 8,  xb + 2 * NN + nb);
        cp4(sa + 12, xb + pt);
        cp4(sa + 16, xb + NN + pt);
        cp4(sa + 20, xb + 2 * NN + pt);
        asm volatile("cp.async.commit_group;");
        int pt1 = n0 + 2 + h;
        nbn = g_idx[(gbase + pt1) * KNN + t];
    }

    for (int p = 0; p < PTS; p += 2) {
        int cur = (p >> 1) & 1;
        int pt = n0 + p + h;
        int gi = gbase + pt;
        if (gat) {
            if (p + 2 < PTS) {
                int ptn = n0 + p + 2 + h;
                unsigned sa = (unsigned)__cvta_generic_to_shared(&sraw[cur ^ 1][h][t][0]);
                cp4(sa + 0,  xb + nbn);
                cp4(sa + 4,  xb + NN + nbn);
                cp4(sa + 8,  xb + 2 * NN + nbn);
                cp4(sa + 12, xb + ptn);
                cp4(sa + 16, xb + NN + ptn);
                cp4(sa + 20, xb + 2 * NN + ptn);
            }
            asm volatile("cp.async.commit_group;");
            int pt2 = (p + 4 < PTS) ? (n0 + p + 4 + h) : n0;
            nbn = g_idx[(gbase + pt2) * KNN + t];
            asm volatile("cp.async.wait_group 1;");
        }
        __syncthreads();
#pragma unroll
        for (int i = 0; i < 10; i++) {
            int k = kb + 2 * i;
            const float* e = sraw[cur][h][k];
            float hv = e[0] * wt[0];
            hv = fmaf(e[1], wt[1], hv);
            hv = fmaf(e[2], wt[2], hv);
            hv = fmaf(e[3], wt[3], hv);
            hv = fmaf(e[4], wt[4], hv);
            hv = fmaf(e[5], wt[5], hv);
            float v = fmaf(s1, hv, sh1);
            sg[h][k][col] = fmaxf(v, SLOPE * v);
        }
        __syncthreads();
        float mx = -CUDART_INF_F, mn = CUDART_INF_F;
#pragma unroll 2
        for (int k = 0; k < KNN; k++) {
            const ulonglong2* gp =
                reinterpret_cast<const ulonglong2*>(&sg[h][k][jh * 36]);
            ull a0 = 0ull, a1 = 0ull, a2 = 0ull, a3 = 0ull;
#pragma unroll
            for (int i = 0; i < 8; i += 2) {
                ulonglong2 gA = gp[i];
                ulonglong2 gB = gp[i + 1];
                fma2(a0, gA.x, w2pk[2 * i + 0]);
                fma2(a1, gA.y, w2pk[2 * i + 1]);
                fma2(a2, gB.x, w2pk[2 * i + 2]);
                fma2(a3, gB.y, w2pk[2 * i + 3]);
            }
            ull s = add2(add2(a0, a1), add2(a2, a3));
            float flo, fhi;
            unpack2(s, flo, fhi);
            float hsum = flo + fhi;
            float other = __shfl_xor_sync(0xffffffffu, hsum, 1);
            float hv = hsum + other;
            mx = fmaxf(mx, hv);
            mn = fminf(mn, hv);
            if (jh == 0) { sum2 += hv; ssq2 = fmaf(hv, hv, ssq2); }
        }
        if (jh == 0) {
            g_maxb[gi * 64 + cg] = mx;
            g_minb[gi * 64 + cg] = mn;
        }
    }

    __syncthreads();
    if (jh == 0) {
        atomicAdd(&schanS[cg], sum2);
        atomicAdd(&schanQ[cg], ssq2);
    }
    __syncthreads();
    if (tid < 64) {
        atomicAdd(&g_sum2[tid],   schanS[tid]);
        atomicAdd(&g_sumsq2[tid], schanQ[tid]);
    }
}

__global__ void stats2_kernel(const float* __restrict__ gamma2,
                              const float* __restrict__ beta2) {
    int c = threadIdx.x;
    if (c >= 64) return;
    float mean = g_sum2[c] / NTOT;
    float var = g_sumsq2[c] / NTOT - mean * mean;
    float s = gamma2[c] * rsqrtf(var + EPSV);
    g_scale2[c] = s;
    g_shift2[c] = fmaf(-mean, s, beta2[c]);
}

__global__ __launch_bounds__(256) void out_kernel(float* __restrict__ out) {
    __shared__ float tile[64][65];
    int b = blockIdx.y;
    int n0 = blockIdx.x * 64;
    int tid = threadIdx.x;
#pragma unroll
    for (int i = 0; i < 16; i++) {
        int flat = i * 256 + tid;
        int cc = flat & 63;
        int nl = flat >> 6;
        float s = g_scale2[cc];
        int gi = (b * NN + n0 + nl) * 64 + cc;
        float v;
        if (s >= 0.f) v = g_maxb[gi]; else v = g_minb[gi];
        float u = fmaf(s, v, g_shift2[cc]);
        tile[nl][cc] = fmaxf(u, SLOPE * u);
    }
    __syncthreads();
#pragma unroll
    for (int i = 0; i < 16; i++) {
        int flat = i * 256 + tid;
        int nl = flat & 63;
        int cc = flat >> 6;
        out[(b * 64 + cc) * NN + n0 + nl] = tile[nl][cc];
    }
}

extern "C" void kernel_launch(void* const* d_in, const int* in_sizes, int n_in,
                              void* d_out, int out_size) {
    const float* x      = (const float*)d_in[0];
    const float* W1     = (const float*)d_in[1];
    const float* gamma1 = (const float*)d_in[2];
    const float* beta1  = (const float*)d_in[3];
    const float* W2     = (const float*)d_in[4];
    const float* gamma2 = (const float*)d_in[5];
    const float* beta2  = (const float*)d_in[6];
    float* out = (float*)d_out;

    zero_kernel<<<1, 64>>>();
    knn_kernel<<<dim3(NN / 64, BB), 128>>>(x);
    stats1_kernel<<<1, 64>>>(W1, gamma1, beta1);
    main_kernel<<<BB * NN / PTS, 256>>>(x, W1, W2);
    stats2_kernel<<<1, 64>>>(gamma2, beta2);
    out_kernel<<<dim3(NN / 64, BB), 256>>>(out);
}